// round 9
// baseline (speedup 1.0000x reference)
#include <cuda_runtime.h>

// CBOW hierarchical softmax loss, fused single-block kernel.
// Inputs (metadata order):
//   d_in[0] context_idx  int32[10]
//   d_in[1] path_indices int32[17]
//   d_in[2] code_bits    int32[17]
//   d_in[3] ctx_emb      float32[100000*512]
//   d_in[4] node_emb     float32[200000*512]
// Output: float32[1] = loss

#define EMBED   512
#define WINDOW  10
#define PATHLEN 17
#define EPS     1e-9f
#define NTHREADS (PATHLEN * 32)   // 544: one warp per path
#define PSTRIDE 19                // gcd(19,32)=1 -> conflict-free both ways

__global__ __launch_bounds__(NTHREADS, 1)
void cbow_hs_kernel(const int* __restrict__ ctx_idx,
                    const int* __restrict__ path_idx,
                    const int* __restrict__ code_bits,
                    const float* __restrict__ ctx_emb,
                    const float* __restrict__ node_emb,
                    float* __restrict__ out)
{
    __shared__ float h_s[EMBED];
    __shared__ float partials[32][PSTRIDE];  // [lane][warp], 17 cols used
    __shared__ float terms[20];              // 17 used, float4-aligned

    const int tid  = threadIdx.x;
    const int wid  = tid >> 5;      // 0..16 == path id
    const int lane = tid & 31;

    // ---- Issue ALL index loads first, then all row gathers, so the two
    // dependent L2/DRAM round-trips stay fully overlapped. ----
    const int pi = __ldg(&path_idx[wid]);
    // Warp 0 needs code bits lane-parallel for the tail (lane p -> path p).
    int cb_l = 0;
    if (wid == 0) cb_l = __ldg(&code_bits[lane < PATHLEN ? lane : 0]);

    // Node row for this warp's path: 512 floats = 4 x float4 per lane.
    const float4* nrow = (const float4*)(node_emb + (long)pi * EMBED);
    float4 nv[4];
    #pragma unroll
    for (int i = 0; i < 4; i++)
        nv[i] = __ldg(&nrow[lane + 32 * i]);

    // h: 128 threads x float4 -> 10 LDG.128 each. Thread t owns dims
    // [4t, 4t+4). 1/WINDOW folded in here, off the critical tail.
    if (tid < EMBED / 4) {
        const int4 c0 = __ldg((const int4*)ctx_idx);        // ctx_idx[0..3]
        const int4 c1 = __ldg((const int4*)ctx_idx + 1);    // ctx_idx[4..7]
        const int2 c2 = __ldg((const int2*)(ctx_idx + 8));  // ctx_idx[8..9]
        const float4* ce = (const float4*)ctx_emb;
        const int     q  = EMBED / 4;

        float4 v0 = __ldg(&ce[(long)c0.x * q + tid]);
        float4 v1 = __ldg(&ce[(long)c0.y * q + tid]);
        float4 v2 = __ldg(&ce[(long)c0.z * q + tid]);
        float4 v3 = __ldg(&ce[(long)c0.w * q + tid]);
        float4 v4 = __ldg(&ce[(long)c1.x * q + tid]);
        float4 v5 = __ldg(&ce[(long)c1.y * q + tid]);
        float4 v6 = __ldg(&ce[(long)c1.z * q + tid]);
        float4 v7 = __ldg(&ce[(long)c1.w * q + tid]);
        float4 v8 = __ldg(&ce[(long)c2.x * q + tid]);
        float4 v9 = __ldg(&ce[(long)c2.y * q + tid]);

        const float inv = 1.0f / WINDOW;
        float4 hv;
        hv.x = (((v0.x + v1.x) + (v2.x + v3.x)) + ((v4.x + v5.x) + (v6.x + v7.x)) + (v8.x + v9.x)) * inv;
        hv.y = (((v0.y + v1.y) + (v2.y + v3.y)) + ((v4.y + v5.y) + (v6.y + v7.y)) + (v8.y + v9.y)) * inv;
        hv.z = (((v0.z + v1.z) + (v2.z + v3.z)) + ((v4.z + v5.z) + (v6.z + v7.z)) + (v8.z + v9.z)) * inv;
        hv.w = (((v0.w + v1.w) + (v2.w + v3.w)) + ((v4.w + v5.w) + (v6.w + v7.w)) + (v8.w + v9.w)) * inv;
        ((float4*)h_s)[tid] = hv;
    }
    __syncthreads();

    // ---- Per-lane partial dot (16 elements), straight to smem: NO warp
    // shuffle tree on the producer path. ----
    const float4* h4 = (const float4*)h_s;
    float d0, d1, d2, d3;
    {
        float4 hh;
        hh = h4[lane];       d0 = nv[0].x*hh.x + nv[0].y*hh.y + nv[0].z*hh.z + nv[0].w*hh.w;
        hh = h4[lane + 32];  d1 = nv[1].x*hh.x + nv[1].y*hh.y + nv[1].z*hh.z + nv[1].w*hh.w;
        hh = h4[lane + 64];  d2 = nv[2].x*hh.x + nv[2].y*hh.y + nv[2].z*hh.z + nv[2].w*hh.w;
        hh = h4[lane + 96];  d3 = nv[3].x*hh.x + nv[3].y*hh.y + nv[3].z*hh.z + nv[3].w*hh.w;
    }
    partials[lane][wid] = (d0 + d1) + (d2 + d3);

    if (wid != 0) {
        asm volatile("bar.arrive 1, %0;" :: "r"(NTHREADS) : "memory");
    } else {
        asm volatile("bar.sync 1, %0;" :: "r"(NTHREADS) : "memory");

        // Warp 0, lane p (<17): reduce warp p's 32 partials. Column reads
        // are conflict-free (consecutive banks at each row j).
        float a0 = 0.f, a1 = 0.f, a2 = 0.f, a3 = 0.f;
        if (lane < PATHLEN) {
            #pragma unroll
            for (int j = 0; j < 32; j += 4) {
                a0 += partials[j    ][lane];
                a1 += partials[j + 1][lane];
                a2 += partials[j + 2][lane];
                a3 += partials[j + 3][lane];
            }
        }
        const float dot = (a0 + a1) + (a2 + a3);

        // Lane-parallel loss terms: prob = sigmoid(dot) if bit==1 else
        // 1-sigmoid(dot); term = -log(prob + EPS).
        const float sx   = (cb_l == 1) ? -dot : dot;
        const float prob = __fdividef(1.0f, 1.0f + __expf(sx));
        const float term = -__logf(prob + EPS);
        if (lane < PATHLEN) terms[lane] = term;
        __syncwarp();

        // Lane 0: vector-load the 17 terms, register tree sum, one STG.
        if (lane == 0) {
            const float4 t0 = *(const float4*)&terms[0];
            const float4 t1 = *(const float4*)&terms[4];
            const float4 t2 = *(const float4*)&terms[8];
            const float4 t3 = *(const float4*)&terms[12];
            const float s01 = (t0.x + t0.y) + (t0.z + t0.w)
                            + (t1.x + t1.y) + (t1.z + t1.w);
            const float s23 = (t2.x + t2.y) + (t2.z + t2.w)
                            + (t3.x + t3.y) + (t3.z + t3.w);
            out[0] = s01 + s23 + terms[16];
        }
    }
}

extern "C" void kernel_launch(void* const* d_in, const int* in_sizes, int n_in,
                              void* d_out, int out_size)
{
    const int*   ctx_idx   = (const int*)d_in[0];
    const int*   path_idx  = (const int*)d_in[1];
    const int*   code_bits = (const int*)d_in[2];
    const float* ctx_emb   = (const float*)d_in[3];
    const float* node_emb  = (const float*)d_in[4];
    float*       out       = (float*)d_out;

    cbow_hs_kernel<<<1, NTHREADS>>>(ctx_idx, path_idx, code_bits,
                                    ctx_emb, node_emb, out);
}

// round 10
// speedup vs baseline: 1.0253x; 1.0253x over previous
#include <cuda_runtime.h>

// CBOW hierarchical softmax loss, fused single-block kernel.
// Inputs (metadata order):
//   d_in[0] context_idx  int32[10]
//   d_in[1] path_indices int32[17]
//   d_in[2] code_bits    int32[17]
//   d_in[3] ctx_emb      float32[100000*512]
//   d_in[4] node_emb     float32[200000*512]
// Output: float32[1] = loss

#define EMBED   512
#define WINDOW  10
#define PATHLEN 17
#define EPS     1e-9f
#define NTHREADS (PATHLEN * 32)   // 544: one warp per path

__device__ __forceinline__ float warp_sum(float v) {
    #pragma unroll
    for (int off = 16; off; off >>= 1)
        v += __shfl_xor_sync(0xffffffffu, v, off);
    return v;
}

__global__ __launch_bounds__(NTHREADS, 1)
void cbow_hs_kernel(const int* __restrict__ ctx_idx,
                    const int* __restrict__ path_idx,
                    const int* __restrict__ code_bits,
                    const float* __restrict__ ctx_emb,
                    const float* __restrict__ node_emb,
                    float* __restrict__ out)
{
    __shared__ float h_s[EMBED];
    __shared__ float terms[20];     // 17 used, float4-aligned

    const int tid  = threadIdx.x;
    const int wid  = tid >> 5;      // 0..16 == path id
    const int lane = tid & 31;

    // ---- Issue ALL index loads first, then all row gathers, so the two
    // dependent L2/DRAM round-trips stay fully overlapped. ----
    const int  pi = __ldg(&path_idx[wid]);
    const int  cb = __ldg(&code_bits[wid]);

    // Node row for this warp's path: 512 floats = 4 x float4 per lane.
    const float4* nrow = (const float4*)(node_emb + (long)pi * EMBED);
    float4 nv[4];
    #pragma unroll
    for (int i = 0; i < 4; i++)
        nv[i] = __ldg(&nrow[lane + 32 * i]);

    // h: 128 threads x float4 -> 10 LDG.128 each (40 warp-instructions).
    // Thread t owns dims [4t, 4t+4). 1/WINDOW folded in here, off the
    // post-shuffle critical path.
    if (tid < EMBED / 4) {
        const int4 c0 = __ldg((const int4*)ctx_idx);        // ctx_idx[0..3]
        const int4 c1 = __ldg((const int4*)ctx_idx + 1);    // ctx_idx[4..7]
        const int2 c2 = __ldg((const int2*)(ctx_idx + 8));  // ctx_idx[8..9]
        const float4* ce = (const float4*)ctx_emb;
        const int     q  = EMBED / 4;                       // 128 float4 per row

        float4 v0 = __ldg(&ce[(long)c0.x * q + tid]);
        float4 v1 = __ldg(&ce[(long)c0.y * q + tid]);
        float4 v2 = __ldg(&ce[(long)c0.z * q + tid]);
        float4 v3 = __ldg(&ce[(long)c0.w * q + tid]);
        float4 v4 = __ldg(&ce[(long)c1.x * q + tid]);
        float4 v5 = __ldg(&ce[(long)c1.y * q + tid]);
        float4 v6 = __ldg(&ce[(long)c1.z * q + tid]);
        float4 v7 = __ldg(&ce[(long)c1.w * q + tid]);
        float4 v8 = __ldg(&ce[(long)c2.x * q + tid]);
        float4 v9 = __ldg(&ce[(long)c2.y * q + tid]);

        const float inv = 1.0f / WINDOW;
        float4 hv;      // pairwise tree add, short dependency depth
        hv.x = (((v0.x + v1.x) + (v2.x + v3.x)) + ((v4.x + v5.x) + (v6.x + v7.x)) + (v8.x + v9.x)) * inv;
        hv.y = (((v0.y + v1.y) + (v2.y + v3.y)) + ((v4.y + v5.y) + (v6.y + v7.y)) + (v8.y + v9.y)) * inv;
        hv.z = (((v0.z + v1.z) + (v2.z + v3.z)) + ((v4.z + v5.z) + (v6.z + v7.z)) + (v8.z + v9.z)) * inv;
        hv.w = (((v0.w + v1.w) + (v2.w + v3.w)) + ((v4.w + v5.w) + (v6.w + v7.w)) + (v8.w + v9.w)) * inv;
        ((float4*)h_s)[tid] = hv;
    }
    __syncthreads();

    // ---- Dot: registers x smem; 4 independent partial chains, pairwise
    // combine, then the in-warp shuffle tree. ----
    const float4* h4 = (const float4*)h_s;
    float d0, d1, d2, d3;
    {
        float4 hh;
        hh = h4[lane];       d0 = nv[0].x*hh.x + nv[0].y*hh.y + nv[0].z*hh.z + nv[0].w*hh.w;
        hh = h4[lane + 32];  d1 = nv[1].x*hh.x + nv[1].y*hh.y + nv[1].z*hh.z + nv[1].w*hh.w;
        hh = h4[lane + 64];  d2 = nv[2].x*hh.x + nv[2].y*hh.y + nv[2].z*hh.z + nv[2].w*hh.w;
        hh = h4[lane + 96];  d3 = nv[3].x*hh.x + nv[3].y*hh.y + nv[3].z*hh.z + nv[3].w*hh.w;
    }
    const float dot = warp_sum((d0 + d1) + (d2 + d3));

    // Branch-free loss term on all lanes:
    // prob = sigmoid(dot) if bit==1 else 1-sigmoid(dot); term = -log(prob+EPS)
    const float sx   = (cb == 1) ? -dot : dot;
    const float prob = __fdividef(1.0f, 1.0f + __expf(sx));
    const float term = -__logf(prob + EPS);
    if (lane == 0) terms[wid] = term;

    if (wid != 0) {
        // Producers: publish term, arrive (non-blocking), done.
        asm volatile("bar.arrive 1, %0;" :: "r"(NTHREADS) : "memory");
    } else {
        // Warp 0: wait for the other 16 terms, then lane 0 does a short
        // vector-LDS register-tree sum (~60 cyc vs ~130 for a shuffle tree).
        asm volatile("bar.sync 1, %0;" :: "r"(NTHREADS) : "memory");
        if (lane == 0) {
            const float4 t0 = *(const float4*)&terms[0];
            const float4 t1 = *(const float4*)&terms[4];
            const float4 t2 = *(const float4*)&terms[8];
            const float4 t3 = *(const float4*)&terms[12];
            const float s01 = ((t0.x + t0.y) + (t0.z + t0.w))
                            + ((t1.x + t1.y) + (t1.z + t1.w));
            const float s23 = ((t2.x + t2.y) + (t2.z + t2.w))
                            + ((t3.x + t3.y) + (t3.z + t3.w));
            out[0] = (s01 + s23) + terms[16];
        }
    }
}

extern "C" void kernel_launch(void* const* d_in, const int* in_sizes, int n_in,
                              void* d_out, int out_size)
{
    const int*   ctx_idx   = (const int*)d_in[0];
    const int*   path_idx  = (const int*)d_in[1];
    const int*   code_bits = (const int*)d_in[2];
    const float* ctx_emb   = (const float*)d_in[3];
    const float* node_emb  = (const float*)d_in[4];
    float*       out       = (float*)d_out;

    cbow_hs_kernel<<<1, NTHREADS>>>(ctx_idx, path_idx, code_bits,
                                    ctx_emb, node_emb, out);
}